// round 2
// baseline (speedup 1.0000x reference)
#include <cuda_runtime.h>
#include <cuda_fp16.h>

// ---------------- problem constants ----------------
#define C_      64
#define K_      15
#define H_      32
#define SIGMA_INV (1.0f / 0.7f)
#define BN_EPS  1e-5f
#define MAXN    50176

// ---------------- scratch ----------------
__device__ float g_h[MAXN * C_];
__device__ float g_part[1024 * 128];
__device__ float g_scale[C_];
__device__ float g_shift[C_];

// ---------------- f32x2 helpers (sm_103a) ----------------
__device__ __forceinline__ unsigned long long pack2(float x, float y) {
    unsigned long long r;
    asm("mov.b64 %0, {%1, %2};" : "=l"(r) : "f"(x), "f"(y));
    return r;
}
__device__ __forceinline__ void unpack2(unsigned long long v, float& x, float& y) {
    asm("mov.b64 {%0, %1}, %2;" : "=f"(x), "=f"(y) : "l"(v));
}
__device__ __forceinline__ void fma2(unsigned long long& acc,
                                     unsigned long long a, unsigned long long b) {
    asm("fma.rn.f32x2 %0, %1, %2, %0;" : "+l"(acc) : "l"(a), "l"(b));
}
__device__ __forceinline__ void add2(unsigned long long& acc, unsigned long long a) {
    asm("add.rn.f32x2 %0, %0, %1;" : "+l"(acc) : "l"(a));
}

// ================= K1: h = s_feats @ W1 (row-pair f32x2), BN partials =========
// 64 rows/block, 256 threads: c = tid&63 (output col), rb = (tid>>6)*16 (rows).
__global__ void __launch_bounds__(256) k1_feat_mm(
    const float* __restrict__ s_feats, const float* __restrict__ W1, int N)
{
    __shared__ float W1s[64 * 64];
    __shared__ float feat_t[64 * 66];   // [cp][r], stride 66 (even -> LDS.64 ok)
    __shared__ float red[256];

    const int tid  = threadIdx.x;
    const int row0 = blockIdx.x * 64;

    for (int i = tid; i < 4096; i += 256) W1s[i] = W1[i];

    #pragma unroll
    for (int it = 0; it < 4; it++) {
        int idx = it * 256 + tid;            // 0..1023
        int r   = idx >> 4;                  // 0..63
        int c0  = (idx & 15) * 4;
        float4 v = make_float4(0.f, 0.f, 0.f, 0.f);
        if (row0 + r < N)
            v = *reinterpret_cast<const float4*>(s_feats + (row0 + r) * 64 + c0);
        feat_t[(c0 + 0) * 66 + r] = v.x;
        feat_t[(c0 + 1) * 66 + r] = v.y;
        feat_t[(c0 + 2) * 66 + r] = v.z;
        feat_t[(c0 + 3) * 66 + r] = v.w;
    }
    __syncthreads();

    const int c  = tid & 63;
    const int rb = (tid >> 6) * 16;
    unsigned long long acc[8];
    #pragma unroll
    for (int p = 0; p < 8; p++) acc[p] = 0ull;

    #pragma unroll 4
    for (int cp = 0; cp < 64; cp++) {
        float w = W1s[cp * 64 + c];
        unsigned long long w2 = pack2(w, w);
        const unsigned long long* ar =
            reinterpret_cast<const unsigned long long*>(feat_t + cp * 66 + rb);
        #pragma unroll
        for (int p = 0; p < 8; p++) fma2(acc[p], ar[p], w2);
    }

    unsigned long long s2 = 0ull, q2 = 0ull;
    #pragma unroll
    for (int p = 0; p < 8; p++) {
        float x0, x1;
        unpack2(acc[p], x0, x1);
        int r = row0 + rb + 2 * p;
        if (r < N)     g_h[r * 64 + c] = x0;
        if (r + 1 < N) g_h[(r + 1) * 64 + c] = x1;
        add2(s2, acc[p]);           // out-of-range rows contributed zeros
        fma2(q2, acc[p], acc[p]);
    }
    float sx, sy, qx, qy;
    unpack2(s2, sx, sy);
    unpack2(q2, qx, qy);

    red[tid] = sx + sy;
    __syncthreads();
    if (tid < 64)
        g_part[blockIdx.x * 128 + tid] =
            red[tid] + red[tid + 64] + red[tid + 128] + red[tid + 192];
    __syncthreads();
    red[tid] = qx + qy;
    __syncthreads();
    if (tid < 64)
        g_part[blockIdx.x * 128 + 64 + tid] =
            red[tid] + red[tid + 64] + red[tid + 128] + red[tid + 192];
}

// ================= K2: finalize BN =================
__global__ void __launch_bounds__(256) k2_bn(
    const float* __restrict__ gamma, const float* __restrict__ beta,
    int N, int nb)
{
    __shared__ float red[256];
    const int tid  = threadIdx.x;
    const int c    = tid & 63;
    const int part = tid >> 6;

    float s = 0.f, q = 0.f;
    for (int b = part; b < nb; b += 4) {
        s += g_part[b * 128 + c];
        q += g_part[b * 128 + 64 + c];
    }
    red[tid] = s;
    __syncthreads();
    float sum = 0.f;
    if (tid < 64) sum = red[tid] + red[tid + 64] + red[tid + 128] + red[tid + 192];
    __syncthreads();
    red[tid] = q;
    __syncthreads();
    if (tid < 64) {
        float sq  = red[tid] + red[tid + 64] + red[tid + 128] + red[tid + 192];
        float inv = 1.f / (float)N;
        float mu  = sum * inv;
        float var = sq * inv - mu * mu;
        float sc  = gamma[tid] * rsqrtf(var + BN_EPS);
        g_scale[tid] = sc;
        g_shift[tid] = beta[tid] - mu * sc;
    }
}

// ================= K3: fused weights-GEMM + gather + aggregate =================
// 32 queries/block, 512 threads, fp16 weight tile -> ~78KB smem -> 2 blocks/SM.
#define K3_SMEM_BYTES 79616

__global__ void __launch_bounds__(512, 2) k3_main(
    const float* __restrict__ q_pts, const float* __restrict__ s_pts,
    const float* __restrict__ s_feats, const int* __restrict__ neighb_inds,
    const float* __restrict__ kernel_points,
    const float* __restrict__ W2, const float* __restrict__ b2,
    float* __restrict__ out, int N)
{
    extern __shared__ float sm[];
    float*  a_t    = sm;                                   // 64*34 f  (8704B)
    __half* w_h    = (__half*)(sm + 2176);                 // 32*15*64 h (61440B)
    float*  infl_s = (float*)((char*)w_h + 61440);         // 1024 f
    int*    ind_s  = (int*)(infl_s + 1024);                // 1024 i
    float*  kp_s   = (float*)(ind_s + 1024);               // 48 f
    unsigned char* nn_s = (unsigned char*)(kp_s + 48);     // 1024 B

    const int tid = threadIdx.x;
    const int m0  = blockIdx.x * 32;

    if (tid < 45) kp_s[tid] = kernel_points[tid];
    __syncthreads();

    // ---- phase 1: a = leakyrelu(BN(h)) transposed into a_t[c][m] ----
    #pragma unroll
    for (int it = 0; it < 4; it++) {
        int i = it * 512 + tid;
        int c = i & 63, m = i >> 6;
        int gm = m0 + m;
        float v = 0.f;
        if (gm < N) {
            v = fmaf(g_h[gm * 64 + c], g_scale[c], g_shift[c]);
            v = (v > 0.f) ? v : 0.1f * v;
        }
        a_t[c * 34 + m] = v;
    }

    // ---- phase 2: neighbor 1-NN kernel point + influence ----
    #pragma unroll
    for (int it = 0; it < 2; it++) {
        int i = it * 512 + tid;
        int m = i >> 5, h = i & 31;
        int gm = m0 + m;
        int ind = 0, kb = 0;
        float infl = 0.f;
        if (gm < N) {
            int id = neighb_inds[gm * 32 + h];
            ind = id;
            float qx = q_pts[gm * 3 + 0];
            float qy = q_pts[gm * 3 + 1];
            float qz = q_pts[gm * 3 + 2];
            float nx = s_pts[id * 3 + 0] - qx;
            float ny = s_pts[id * 3 + 1] - qy;
            float nz = s_pts[id * 3 + 2] - qz;
            float best = 1e30f;
            #pragma unroll
            for (int k = 0; k < 15; k++) {
                float dx = nx - kp_s[k * 3 + 0];
                float dy = ny - kp_s[k * 3 + 1];
                float dz = nz - kp_s[k * 3 + 2];
                float d = fmaf(dx, dx, fmaf(dy, dy, dz * dz));
                if (d < best) { best = d; kb = k; }
            }
            infl = fmaxf(0.f, 1.f - sqrtf(best) * SIGMA_INV);
        }
        ind_s[i]  = ind;
        infl_s[i] = infl;
        nn_s[i]   = (unsigned char)kb;
    }
    __syncthreads();

    // ---- phase 3: w[m][k][c] = a[m]@W2 + b2, fp16 store; 1 col x 16 m-pairs ----
    #pragma unroll
    for (int pass = 0; pass < 2; pass++) {
        int j = pass * 512 + tid;
        if (j < 960) {
            unsigned long long acc[16];
            {
                float b = __ldg(b2 + j);
                unsigned long long pb = pack2(b, b);
                #pragma unroll
                for (int p = 0; p < 16; p++) acc[p] = pb;
            }
            #pragma unroll 4
            for (int cp = 0; cp < 64; cp++) {
                float w = __ldg(W2 + cp * 960 + j);
                unsigned long long w2 = pack2(w, w);
                const unsigned long long* ar =
                    reinterpret_cast<const unsigned long long*>(a_t + cp * 34);
                #pragma unroll
                for (int p = 0; p < 16; p++) fma2(acc[p], ar[p], w2);
            }
            const int kk = j >> 6, c0 = j & 63;
            #pragma unroll
            for (int p = 0; p < 16; p++) {
                float x0, x1;
                unpack2(acc[p], x0, x1);
                w_h[(((2 * p) * 15 + kk) << 6) + c0]     = __float2half_rn(x0);
                w_h[(((2 * p + 1) * 15 + kk) << 6) + c0] = __float2half_rn(x1);
            }
        }
    }
    __syncthreads();

    // ---- phase 4: gather + aggregate; warp owns 2 queries; float2 lanes ----
    {
        const int wid = tid >> 5, lane = tid & 31;
        #pragma unroll
        for (int mi = 0; mi < 2; mi++) {
            int mm = wid * 2 + mi;
            int gm = m0 + mm;
            if (gm >= N) continue;
            float ox = 0.f, oy = 0.f;
            const int base = mm << 5;
            #pragma unroll 4
            for (int h = 0; h < 32; h++) {
                float fl = infl_s[base + h];
                int   id = ind_s[base + h];
                int   k  = nn_s[base + h];
                float2 f = *reinterpret_cast<const float2*>(
                    s_feats + id * 64 + 2 * lane);
                __half2 wh = *reinterpret_cast<const __half2*>(
                    w_h + ((mm * 15 + k) << 6) + 2 * lane);
                float2 wf = __half22float2(wh);
                ox = fmaf(f.x, wf.x * fl, ox);
                oy = fmaf(f.y, wf.y * fl, oy);
            }
            *reinterpret_cast<float2*>(out + gm * 64 + 2 * lane) =
                make_float2(ox, oy);
        }
    }
}

// ================= launch =================
extern "C" void kernel_launch(void* const* d_in, const int* in_sizes, int n_in,
                              void* d_out, int out_size)
{
    const float* q_pts   = (const float*)d_in[0];
    const float* s_pts   = (const float*)d_in[1];
    const float* s_feats = (const float*)d_in[2];
    const int*   neighb  = (const int*)d_in[3];
    const float* kp      = (const float*)d_in[4];
    const float* W1      = (const float*)d_in[5];
    const float* gamma   = (const float*)d_in[6];
    const float* beta    = (const float*)d_in[7];
    const float* W2      = (const float*)d_in[8];
    const float* b2      = (const float*)d_in[9];
    float* out = (float*)d_out;

    const int N   = in_sizes[0] / 3;
    const int nb1 = (N + 63) / 64;

    k1_feat_mm<<<nb1, 256>>>(s_feats, W1, N);
    k2_bn<<<1, 256>>>(gamma, beta, N, nb1);

    cudaFuncSetAttribute(k3_main, cudaFuncAttributeMaxDynamicSharedMemorySize,
                         K3_SMEM_BYTES);
    const int nb3 = (N + 31) / 32;
    k3_main<<<nb3, 512, K3_SMEM_BYTES>>>(q_pts, s_pts, s_feats, neighb, kp,
                                         W2, b2, out, N);
}

// round 4
// speedup vs baseline: 1.7381x; 1.7381x over previous
#include <cuda_runtime.h>
#include <cuda_fp16.h>
#include <cstdint>

// ---------------- problem constants ----------------
#define SIGMA_INV (1.0f / 0.7f)
#define BN_EPS  1e-5f
#define MAXN    50176

// ---------------- scratch ----------------
__device__ float  g_h[MAXN * 64];            // pre-BN activations
__device__ float  g_part[512 * 128];         // BN partials
__device__ float  g_scale[64];
__device__ float  g_shift[64];
__device__ __half g_a[MAXN * 64];            // fp16 post-activation
__device__ __half g_feats16[MAXN * 64];      // fp16 mirror of s_feats
__device__ __half g_w2t[960 * 64];           // W2^T fp16 [n][k]
__device__ __half g_cw[(size_t)MAXN * 960];  // conv weights fp16 [m][k*64+c]

// ---------------- f32x2 helpers ----------------
__device__ __forceinline__ unsigned long long pack2(float x, float y) {
    unsigned long long r;
    asm("mov.b64 %0, {%1, %2};" : "=l"(r) : "f"(x), "f"(y));
    return r;
}
__device__ __forceinline__ void unpack2(unsigned long long v, float& x, float& y) {
    asm("mov.b64 {%0, %1}, %2;" : "=f"(x), "=f"(y) : "l"(v));
}
__device__ __forceinline__ void fma2(unsigned long long& acc,
                                     unsigned long long a, unsigned long long b) {
    asm("fma.rn.f32x2 %0, %1, %2, %0;" : "+l"(acc) : "l"(a), "l"(b));
}
__device__ __forceinline__ void add2(unsigned long long& acc, unsigned long long a) {
    asm("add.rn.f32x2 %0, %0, %1;" : "+l"(acc) : "l"(a));
}

// ---------------- HMMA m16n8k16 fp16->fp32 ----------------
__device__ __forceinline__ void mma16816(float* c, const uint32_t* a,
                                         uint32_t b0, uint32_t b1) {
    asm volatile(
        "mma.sync.aligned.m16n8k16.row.col.f32.f16.f16.f32 "
        "{%0,%1,%2,%3}, {%4,%5,%6,%7}, {%8,%9}, {%0,%1,%2,%3};"
        : "+f"(c[0]), "+f"(c[1]), "+f"(c[2]), "+f"(c[3])
        : "r"(a[0]), "r"(a[1]), "r"(a[2]), "r"(a[3]), "r"(b0), "r"(b1));
}

// ================= K1: h = s_feats @ W1 + BN partials + fp16 feats mirror =====
// 128 rows/block, 256 threads; thread = 2 cols x 16 rows (8 f32x2 pairs).
#define K1_SMEM_FLOATS (4096 + 64 * 130 + 256)
#define K1_SMEM_BYTES  (K1_SMEM_FLOATS * 4)

__global__ void __launch_bounds__(256) k1_feat_mm(
    const float* __restrict__ s_feats, const float* __restrict__ W1, int N)
{
    extern __shared__ float sm1[];
    float* W1s    = sm1;                 // 64*64
    float* feat_t = sm1 + 4096;          // [k][r] stride 130
    float* red    = feat_t + 64 * 130;   // 256

    const int tid  = threadIdx.x;
    const int row0 = blockIdx.x * 128;

    for (int i = tid; i < 4096; i += 256) W1s[i] = W1[i];

    #pragma unroll
    for (int it = 0; it < 8; it++) {
        int idx = it * 256 + tid;        // 0..2047
        int r   = idx >> 4;              // 0..127
        int c0  = (idx & 15) * 4;
        float4 v = make_float4(0.f, 0.f, 0.f, 0.f);
        if (row0 + r < N) {
            v = *reinterpret_cast<const float4*>(s_feats + (row0 + r) * 64 + c0);
            __half2 h01 = __floats2half2_rn(v.x, v.y);
            __half2 h23 = __floats2half2_rn(v.z, v.w);
            uint2 hp;
            hp.x = *reinterpret_cast<uint32_t*>(&h01);
            hp.y = *reinterpret_cast<uint32_t*>(&h23);
            *reinterpret_cast<uint2*>(g_feats16 + (row0 + r) * 64 + c0) = hp;
        }
        feat_t[(c0 + 0) * 130 + r] = v.x;
        feat_t[(c0 + 1) * 130 + r] = v.y;
        feat_t[(c0 + 2) * 130 + r] = v.z;
        feat_t[(c0 + 3) * 130 + r] = v.w;
    }
    __syncthreads();

    const int cg = tid & 31, rg = tid >> 5;
    const int c0 = cg * 2;
    unsigned long long acc[2][8];
    #pragma unroll
    for (int cc = 0; cc < 2; cc++)
        #pragma unroll
        for (int p = 0; p < 8; p++) acc[cc][p] = 0ull;

    #pragma unroll 4
    for (int cp = 0; cp < 64; cp++) {
        unsigned long long wp =
            *reinterpret_cast<const unsigned long long*>(W1s + cp * 64 + c0);
        float w0, w1;
        unpack2(wp, w0, w1);
        unsigned long long w00 = pack2(w0, w0), w11 = pack2(w1, w1);
        const unsigned long long* ar =
            reinterpret_cast<const unsigned long long*>(feat_t + cp * 130 + rg * 16);
        #pragma unroll
        for (int p = 0; p < 8; p++) {
            unsigned long long a2 = ar[p];
            fma2(acc[0][p], a2, w00);
            fma2(acc[1][p], a2, w11);
        }
    }

    float sv[2], qv[2];
    #pragma unroll
    for (int cc = 0; cc < 2; cc++) {
        unsigned long long s2 = 0ull, q2 = 0ull;
        #pragma unroll
        for (int p = 0; p < 8; p++) {
            float x0, x1;
            unpack2(acc[cc][p], x0, x1);
            int r = row0 + rg * 16 + 2 * p;
            if (r < N)     g_h[r * 64 + c0 + cc] = x0;
            if (r + 1 < N) g_h[(r + 1) * 64 + c0 + cc] = x1;
            add2(s2, acc[cc][p]);              // padded rows are exact zeros
            fma2(q2, acc[cc][p], acc[cc][p]);
        }
        float ax, ay;
        unpack2(s2, ax, ay); sv[cc] = ax + ay;
        unpack2(q2, ax, ay); qv[cc] = ax + ay;
    }

    #pragma unroll
    for (int pass = 0; pass < 4; pass++) {
        float val = (pass < 2) ? sv[pass] : qv[pass - 2];
        __syncthreads();
        red[tid] = val;
        __syncthreads();
        if (tid < 32) {
            float t = 0.f;
            #pragma unroll
            for (int g = 0; g < 8; g++) t += red[g * 32 + tid];
            int c = tid * 2 + (pass & 1);
            g_part[blockIdx.x * 128 + ((pass < 2) ? 0 : 64) + c] = t;
        }
    }
}

// ================= K2: finalize BN =================
__global__ void __launch_bounds__(256) k2_bn(
    const float* __restrict__ gamma, const float* __restrict__ beta, int N, int nb)
{
    __shared__ float red[256];
    const int tid  = threadIdx.x;
    const int c    = tid & 63;
    const int part = tid >> 6;

    float s = 0.f, q = 0.f;
    for (int b = part; b < nb; b += 4) {
        s += g_part[b * 128 + c];
        q += g_part[b * 128 + 64 + c];
    }
    red[tid] = s;
    __syncthreads();
    float sum = 0.f;
    if (tid < 64) sum = red[tid] + red[tid + 64] + red[tid + 128] + red[tid + 192];
    __syncthreads();
    red[tid] = q;
    __syncthreads();
    if (tid < 64) {
        float sq  = red[tid] + red[tid + 64] + red[tid + 128] + red[tid + 192];
        float inv = 1.f / (float)N;
        float mu  = sum * inv;
        float var = sq * inv - mu * mu;
        float sc  = gamma[tid] * rsqrtf(var + BN_EPS);
        g_scale[tid] = sc;
        g_shift[tid] = beta[tid] - mu * sc;
    }
}

// ================= K3a: activation -> fp16 =================
__global__ void __launch_bounds__(256) k3_act(int N)
{
    int p = blockIdx.x * 256 + threadIdx.x;
    if (p >= N * 32) return;
    int c = (p & 31) * 2;
    float2 h  = *reinterpret_cast<const float2*>(g_h + 2 * p);
    float2 sc = *reinterpret_cast<const float2*>(g_scale + c);
    float2 sh = *reinterpret_cast<const float2*>(g_shift + c);
    float x = fmaf(h.x, sc.x, sh.x); x = (x > 0.f) ? x : 0.1f * x;
    float y = fmaf(h.y, sc.y, sh.y); y = (y > 0.f) ? y : 0.1f * y;
    *reinterpret_cast<__half2*>(g_a + 2 * p) = __floats2half2_rn(x, y);
}

// ================= K3b: W2 transpose -> fp16 [n][k] =================
__global__ void __launch_bounds__(256) k3_tr(const float* __restrict__ W2)
{
    int i = blockIdx.x * 256 + threadIdx.x;
    if (i < 960 * 64) {
        int n = i >> 6, c = i & 63;
        g_w2t[i] = __float2half_rn(W2[c * 960 + n]);
    }
}

// ================= K4: HMMA GEMM cw = a @ W2^T + b2 (fp16 out) =================
// Tile 64(M) x 64(N), K=64. 128 threads = 4 warps, warp owns n16 slice.
#define AS_STRIDE 72

__global__ void __launch_bounds__(128) k4_gemm(const float* __restrict__ b2, int N)
{
    __shared__ __half A_s[64 * AS_STRIDE];
    __shared__ __half B_s[64 * AS_STRIDE];

    const int tid  = threadIdx.x;
    const int lane = tid & 31, w = tid >> 5;
    const int row0 = blockIdx.x * 64;
    const int n0   = blockIdx.y * 64;

    #pragma unroll
    for (int it = 0; it < 4; it++) {
        int idx = it * 128 + tid;        // 0..511
        int r = idx >> 3, c8 = idx & 7;
        uint4 v = make_uint4(0u, 0u, 0u, 0u);
        if (row0 + r < N)
            v = *reinterpret_cast<const uint4*>(g_a + (row0 + r) * 64 + c8 * 8);
        *reinterpret_cast<uint4*>(A_s + r * AS_STRIDE + c8 * 8) = v;
    }
    #pragma unroll
    for (int it = 0; it < 4; it++) {
        int idx = it * 128 + tid;
        int r = idx >> 3, c8 = idx & 7;
        uint4 v = *reinterpret_cast<const uint4*>(g_w2t + (n0 + r) * 64 + c8 * 8);
        *reinterpret_cast<uint4*>(B_s + r * AS_STRIDE + c8 * 8) = v;
    }
    __syncthreads();

    float acc[4][2][4];
    #pragma unroll
    for (int i = 0; i < 4; i++)
        #pragma unroll
        for (int j = 0; j < 2; j++)
            #pragma unroll
            for (int q = 0; q < 4; q++) acc[i][j][q] = 0.f;

    const int mrow = lane >> 2;          // 0..7
    const int kcol = (lane & 3) * 2;     // 0,2,4,6

    #pragma unroll
    for (int ks = 0; ks < 4; ks++) {
        const int kb = ks * 16;
        uint32_t a[4][4];
        #pragma unroll
        for (int i = 0; i < 4; i++) {
            const __half* ap = A_s + (i * 16 + mrow) * AS_STRIDE + kb + kcol;
            a[i][0] = *reinterpret_cast<const uint32_t*>(ap);
            a[i][1] = *reinterpret_cast<const uint32_t*>(ap + 8 * AS_STRIDE);
            a[i][2] = *reinterpret_cast<const uint32_t*>(ap + 8);
            a[i][3] = *reinterpret_cast<const uint32_t*>(ap + 8 * AS_STRIDE + 8);
        }
        #pragma unroll
        for (int j = 0; j < 2; j++) {
            const __half* bp = B_s + (w * 16 + j * 8 + mrow) * AS_STRIDE + kb + kcol;
            uint32_t b0 = *reinterpret_cast<const uint32_t*>(bp);
            uint32_t b1 = *reinterpret_cast<const uint32_t*>(bp + 8);
            #pragma unroll
            for (int i = 0; i < 4; i++)
                mma16816(acc[i][j], a[i], b0, b1);
        }
    }

    // epilogue: add bias, fp16, store
    #pragma unroll
    for (int j = 0; j < 2; j++) {
        int ncol = n0 + w * 16 + j * 8 + kcol;
        float bx = __ldg(b2 + ncol);
        float by = __ldg(b2 + ncol + 1);
        #pragma unroll
        for (int i = 0; i < 4; i++) {
            int r = row0 + i * 16 + mrow;
            if (r < N)
                *reinterpret_cast<__half2*>(g_cw + (size_t)r * 960 + ncol) =
                    __floats2half2_rn(acc[i][j][0] + bx, acc[i][j][1] + by);
            if (r + 8 < N)
                *reinterpret_cast<__half2*>(g_cw + (size_t)(r + 8) * 960 + ncol) =
                    __floats2half2_rn(acc[i][j][2] + bx, acc[i][j][3] + by);
        }
    }
}

// ================= K5: gather + influence + aggregate =================
__global__ void __launch_bounds__(512) k5_agg(
    const float* __restrict__ q_pts, const float* __restrict__ s_pts,
    const int* __restrict__ neighb_inds,
    const float* __restrict__ kernel_points, float* __restrict__ out, int N)
{
    __shared__ float kp_s[48];
    __shared__ float infl_s[512];
    __shared__ int   ind_s[512];
    __shared__ unsigned char nn_s[512];

    const int tid = threadIdx.x;
    const int m0  = blockIdx.x * 16;

    if (tid < 45) kp_s[tid] = kernel_points[tid];
    __syncthreads();

    {
        int m = tid >> 5, h = tid & 31;
        int gm = m0 + m;
        int ind = 0, kb = 0;
        float infl = 0.f;
        if (gm < N) {
            int id = neighb_inds[gm * 32 + h];
            if ((unsigned)id < (unsigned)N) {
                ind = id;
                float qx = q_pts[gm * 3 + 0];
                float qy = q_pts[gm * 3 + 1];
                float qz = q_pts[gm * 3 + 2];
                float nx = s_pts[id * 3 + 0] - qx;
                float ny = s_pts[id * 3 + 1] - qy;
                float nz = s_pts[id * 3 + 2] - qz;
                float best = 1e30f;
                #pragma unroll
                for (int k = 0; k < 15; k++) {
                    float dx = nx - kp_s[k * 3 + 0];
                    float dy = ny - kp_s[k * 3 + 1];
                    float dz = nz - kp_s[k * 3 + 2];
                    float d = fmaf(dx, dx, fmaf(dy, dy, dz * dz));
                    if (d < best) { best = d; kb = k; }
                }
                infl = fmaxf(0.f, 1.f - sqrtf(best) * SIGMA_INV);
            }
        }
        ind_s[tid]  = ind;
        infl_s[tid] = infl;
        nn_s[tid]   = (unsigned char)kb;
    }
    __syncthreads();

    {
        const int wid = tid >> 5, lane = tid & 31;
        const int gm = m0 + wid;
        if (gm >= N) return;
        const __half* cw_row = g_cw + (size_t)gm * 960;
        float ox = 0.f, oy = 0.f;
        const int base = wid * 32;
        #pragma unroll 8
        for (int h = 0; h < 32; h++) {
            float fl = infl_s[base + h];
            int   id = ind_s[base + h];
            int   k  = nn_s[base + h];
            __half2 fh = *reinterpret_cast<const __half2*>(
                g_feats16 + id * 64 + 2 * lane);
            __half2 wh = *reinterpret_cast<const __half2*>(
                cw_row + (k << 6) + 2 * lane);
            float2 f  = __half22float2(fh);
            float2 wf = __half22float2(wh);
            ox = fmaf(f.x, wf.x * fl, ox);
            oy = fmaf(f.y, wf.y * fl, oy);
        }
        *reinterpret_cast<float2*>(out + gm * 64 + 2 * lane) = make_float2(ox, oy);
    }
}

// ================= launch =================
extern "C" void kernel_launch(void* const* d_in, const int* in_sizes, int n_in,
                              void* d_out, int out_size)
{
    const float* q_pts   = (const float*)d_in[0];
    const float* s_pts   = (const float*)d_in[1];
    const float* s_feats = (const float*)d_in[2];
    const int*   neighb  = (const int*)d_in[3];
    const float* kp      = (const float*)d_in[4];
    const float* W1      = (const float*)d_in[5];
    const float* gamma   = (const float*)d_in[6];
    const float* beta    = (const float*)d_in[7];
    const float* W2      = (const float*)d_in[8];
    const float* b2      = (const float*)d_in[9];
    float* out = (float*)d_out;

    const int N   = in_sizes[0] / 3;
    const int nb1 = (N + 127) / 128;

    cudaFuncSetAttribute(k1_feat_mm, cudaFuncAttributeMaxDynamicSharedMemorySize,
                         K1_SMEM_BYTES);
    k1_feat_mm<<<nb1, 256, K1_SMEM_BYTES>>>(s_feats, W1, N);
    k2_bn<<<1, 256>>>(gamma, beta, N, nb1);
    k3_act<<<(N * 32 + 255) / 256, 256>>>(N);
    k3_tr<<<240, 256>>>(W2);

    dim3 g4((N + 63) / 64, 15);
    k4_gemm<<<g4, 128>>>(b2, N);

    k5_agg<<<(N + 15) / 16, 512>>>(q_pts, s_pts, neighb, kp, out, N);
}

// round 6
// speedup vs baseline: 1.9361x; 1.1139x over previous
#include <cuda_runtime.h>
#include <cuda_fp16.h>
#include <cstdint>

// ---------------- problem constants ----------------
#define SIGMA_INV (1.0f / 0.7f)
#define BN_EPS  1e-5f
#define MAXN    50176

// ---------------- scratch ----------------
__device__ float  g_h[MAXN * 64];            // pre-BN activations
__device__ float  g_part[512 * 128];         // BN partials
__device__ float  g_scale[64];
__device__ float  g_shift[64];
__device__ __half g_feats16[MAXN * 64];      // fp16 mirror of s_feats
__device__ __half g_w2t[960 * 64];           // W2^T fp16 [n][k]
__device__ __half g_cw[(size_t)MAXN * 960];  // conv weights fp16 [m][k*64+c]

// ---------------- f32x2 helpers ----------------
__device__ __forceinline__ unsigned long long pack2(float x, float y) {
    unsigned long long r;
    asm("mov.b64 %0, {%1, %2};" : "=l"(r) : "f"(x), "f"(y));
    return r;
}
__device__ __forceinline__ void unpack2(unsigned long long v, float& x, float& y) {
    asm("mov.b64 {%0, %1}, %2;" : "=f"(x), "=f"(y) : "l"(v));
}
__device__ __forceinline__ void fma2(unsigned long long& acc,
                                     unsigned long long a, unsigned long long b) {
    asm("fma.rn.f32x2 %0, %1, %2, %0;" : "+l"(acc) : "l"(a), "l"(b));
}
__device__ __forceinline__ void add2(unsigned long long& acc, unsigned long long a) {
    asm("add.rn.f32x2 %0, %0, %1;" : "+l"(acc) : "l"(a));
}

// ---------------- HMMA m16n8k16 fp16->fp32 ----------------
__device__ __forceinline__ void mma16816(float* c, const uint32_t* a,
                                         uint32_t b0, uint32_t b1) {
    asm volatile(
        "mma.sync.aligned.m16n8k16.row.col.f32.f16.f16.f32 "
        "{%0,%1,%2,%3}, {%4,%5,%6,%7}, {%8,%9}, {%0,%1,%2,%3};"
        : "+f"(c[0]), "+f"(c[1]), "+f"(c[2]), "+f"(c[3])
        : "r"(a[0]), "r"(a[1]), "r"(a[2]), "r"(a[3]), "r"(b0), "r"(b1));
}

// ================= K1: h = s_feats @ W1 + BN partials + fp16 feats mirror =====
#define K1_SMEM_FLOATS (4096 + 64 * 130 + 256)
#define K1_SMEM_BYTES  (K1_SMEM_FLOATS * 4)

__global__ void __launch_bounds__(256) k1_feat_mm(
    const float* __restrict__ s_feats, const float* __restrict__ W1, int N)
{
    extern __shared__ float sm1[];
    float* W1s    = sm1;                 // 64*64
    float* feat_t = sm1 + 4096;          // [k][r] stride 130
    float* red    = feat_t + 64 * 130;   // 256

    const int tid  = threadIdx.x;
    const int row0 = blockIdx.x * 128;

    for (int i = tid; i < 4096; i += 256) W1s[i] = W1[i];

    #pragma unroll
    for (int it = 0; it < 8; it++) {
        int idx = it * 256 + tid;
        int r   = idx >> 4;
        int c0  = (idx & 15) * 4;
        float4 v = make_float4(0.f, 0.f, 0.f, 0.f);
        if (row0 + r < N) {
            v = *reinterpret_cast<const float4*>(s_feats + (row0 + r) * 64 + c0);
            __half2 h01 = __floats2half2_rn(v.x, v.y);
            __half2 h23 = __floats2half2_rn(v.z, v.w);
            uint2 hp;
            hp.x = *reinterpret_cast<uint32_t*>(&h01);
            hp.y = *reinterpret_cast<uint32_t*>(&h23);
            *reinterpret_cast<uint2*>(g_feats16 + (row0 + r) * 64 + c0) = hp;
        }
        feat_t[(c0 + 0) * 130 + r] = v.x;
        feat_t[(c0 + 1) * 130 + r] = v.y;
        feat_t[(c0 + 2) * 130 + r] = v.z;
        feat_t[(c0 + 3) * 130 + r] = v.w;
    }
    __syncthreads();

    const int cg = tid & 31, rg = tid >> 5;
    const int c0 = cg * 2;
    unsigned long long acc[2][8];
    #pragma unroll
    for (int cc = 0; cc < 2; cc++)
        #pragma unroll
        for (int p = 0; p < 8; p++) acc[cc][p] = 0ull;

    #pragma unroll 4
    for (int cp = 0; cp < 64; cp++) {
        unsigned long long wp =
            *reinterpret_cast<const unsigned long long*>(W1s + cp * 64 + c0);
        float w0, w1;
        unpack2(wp, w0, w1);
        unsigned long long w00 = pack2(w0, w0), w11 = pack2(w1, w1);
        const unsigned long long* ar =
            reinterpret_cast<const unsigned long long*>(feat_t + cp * 130 + rg * 16);
        #pragma unroll
        for (int p = 0; p < 8; p++) {
            unsigned long long a2 = ar[p];
            fma2(acc[0][p], a2, w00);
            fma2(acc[1][p], a2, w11);
        }
    }

    float sv[2], qv[2];
    #pragma unroll
    for (int cc = 0; cc < 2; cc++) {
        unsigned long long s2 = 0ull, q2 = 0ull;
        #pragma unroll
        for (int p = 0; p < 8; p++) {
            float x0, x1;
            unpack2(acc[cc][p], x0, x1);
            int r = row0 + rg * 16 + 2 * p;
            if (r < N)     g_h[r * 64 + c0 + cc] = x0;
            if (r + 1 < N) g_h[(r + 1) * 64 + c0 + cc] = x1;
            add2(s2, acc[cc][p]);
            fma2(q2, acc[cc][p], acc[cc][p]);
        }
        float ax, ay;
        unpack2(s2, ax, ay); sv[cc] = ax + ay;
        unpack2(q2, ax, ay); qv[cc] = ax + ay;
    }

    #pragma unroll
    for (int pass = 0; pass < 4; pass++) {
        float val = (pass < 2) ? sv[pass] : qv[pass - 2];
        __syncthreads();
        red[tid] = val;
        __syncthreads();
        if (tid < 32) {
            float t = 0.f;
            #pragma unroll
            for (int g = 0; g < 8; g++) t += red[g * 32 + tid];
            int c = tid * 2 + (pass & 1);
            g_part[blockIdx.x * 128 + ((pass < 2) ? 0 : 64) + c] = t;
        }
    }
}

// ================= K2: BN finalize (block 0) + W2 transpose (blocks 1..60) =====
__global__ void __launch_bounds__(256) k2_bn_tr(
    const float* __restrict__ gamma, const float* __restrict__ beta,
    const float* __restrict__ W2, int N, int nb)
{
    const int tid = threadIdx.x;

    if (blockIdx.x == 0) {
        __shared__ float red[256];
        const int c    = tid & 63;
        const int part = tid >> 6;
        float s = 0.f, q = 0.f;
        for (int b = part; b < nb; b += 4) {
            s += g_part[b * 128 + c];
            q += g_part[b * 128 + 64 + c];
        }
        red[tid] = s;
        __syncthreads();
        float sum = 0.f;
        if (tid < 64) sum = red[tid] + red[tid + 64] + red[tid + 128] + red[tid + 192];
        __syncthreads();
        red[tid] = q;
        __syncthreads();
        if (tid < 64) {
            float sq  = red[tid] + red[tid + 64] + red[tid + 128] + red[tid + 192];
            float inv = 1.f / (float)N;
            float mu  = sum * inv;
            float var = sq * inv - mu * mu;
            float sc  = gamma[tid] * rsqrtf(var + BN_EPS);
            g_scale[tid] = sc;
            g_shift[tid] = beta[tid] - mu * sc;
        }
    } else {
        // transpose W2 (64 x 960) -> g_w2t (960 x 64), fp16
        int o0 = (blockIdx.x - 1) * 1024 + tid * 4;
        #pragma unroll
        for (int e = 0; e < 4; e++) {
            int o = o0 + e;                 // < 61440
            int n = o >> 6, c = o & 63;
            g_w2t[o] = __float2half_rn(W2[c * 960 + n]);
        }
    }
}

// ================= K4: persistent-N HMMA GEMM, fused activation ===============
#define AS 72

__global__ void __launch_bounds__(256) k4_gemm(const float* __restrict__ b2, int N)
{
    __shared__ __half A_s[128 * AS];     // 18432 B
    __shared__ __half B_s[64 * AS];      //  9216 B
    __shared__ float  bias_s[960];       //  3840 B

    const int tid  = threadIdx.x;
    const int lane = tid & 31, w = tid >> 5;
    const int wm = w & 1, wn = w >> 1;
    const int row0 = blockIdx.x * 128;

    // prologue: bias + A tile (BN + LeakyReLU fused, fp32 -> fp16)
    for (int i = tid; i < 960; i += 256) bias_s[i] = b2[i];
    {
        const int c0 = (tid & 15) * 4;
        float4 sc = *reinterpret_cast<const float4*>(g_scale + c0);
        float4 sh = *reinterpret_cast<const float4*>(g_shift + c0);
        #pragma unroll
        for (int it = 0; it < 8; it++) {
            int idx = it * 256 + tid;
            int r = idx >> 4;
            float4 v = make_float4(0.f, 0.f, 0.f, 0.f);
            if (row0 + r < N) {
                float4 h = *reinterpret_cast<const float4*>(g_h + (row0 + r) * 64 + c0);
                v.x = fmaf(h.x, sc.x, sh.x); v.x = (v.x > 0.f) ? v.x : 0.1f * v.x;
                v.y = fmaf(h.y, sc.y, sh.y); v.y = (v.y > 0.f) ? v.y : 0.1f * v.y;
                v.z = fmaf(h.z, sc.z, sh.z); v.z = (v.z > 0.f) ? v.z : 0.1f * v.z;
                v.w = fmaf(h.w, sc.w, sh.w); v.w = (v.w > 0.f) ? v.w : 0.1f * v.w;
            }
            __half2 h01 = __floats2half2_rn(v.x, v.y);
            __half2 h23 = __floats2half2_rn(v.z, v.w);
            uint2 hp;
            hp.x = *reinterpret_cast<uint32_t*>(&h01);
            hp.y = *reinterpret_cast<uint32_t*>(&h23);
            *reinterpret_cast<uint2*>(A_s + r * AS + c0) = hp;
        }
    }
    __syncthreads();

    const int mrow = lane >> 2;
    const int kcol = (lane & 3) * 2;

    for (int n0 = 0; n0 < 960; n0 += 64) {
        // load B tile (64 n-rows x 64 k)
        #pragma unroll
        for (int it = 0; it < 2; it++) {
            int idx = it * 256 + tid;        // 0..511
            int r = idx >> 3, c8 = idx & 7;
            uint4 v = *reinterpret_cast<const uint4*>(g_w2t + (n0 + r) * 64 + c8 * 8);
            *reinterpret_cast<uint4*>(B_s + r * AS + c8 * 8) = v;
        }
        __syncthreads();

        float acc[4][2][4];
        #pragma unroll
        for (int i = 0; i < 4; i++)
            #pragma unroll
            for (int j = 0; j < 2; j++)
                #pragma unroll
                for (int q = 0; q < 4; q++) acc[i][j][q] = 0.f;

        #pragma unroll
        for (int ks = 0; ks < 4; ks++) {
            const int kb = ks * 16;
            uint32_t a[4][4];
            #pragma unroll
            for (int i = 0; i < 4; i++) {
                const __half* ap = A_s + (wm * 64 + i * 16 + mrow) * AS + kb + kcol;
                a[i][0] = *reinterpret_cast<const uint32_t*>(ap);
                a[i][1] = *reinterpret_cast<const uint32_t*>(ap + 8 * AS);
                a[i][2] = *reinterpret_cast<const uint32_t*>(ap + 8);
                a[i][3] = *reinterpret_cast<const uint32_t*>(ap + 8 * AS + 8);
            }
            #pragma unroll
            for (int j = 0; j < 2; j++) {
                const __half* bp = B_s + (wn * 16 + j * 8 + mrow) * AS + kb + kcol;
                uint32_t b0 = *reinterpret_cast<const uint32_t*>(bp);
                uint32_t b1 = *reinterpret_cast<const uint32_t*>(bp + 8);
                #pragma unroll
                for (int i = 0; i < 4; i++)
                    mma16816(acc[i][j], a[i], b0, b1);
            }
        }

        // epilogue: bias + fp16 store
        #pragma unroll
        for (int j = 0; j < 2; j++) {
            int col = n0 + wn * 16 + j * 8 + kcol;
            float bx = bias_s[col], by = bias_s[col + 1];
            #pragma unroll
            for (int i = 0; i < 4; i++) {
                int r = row0 + wm * 64 + i * 16 + mrow;
                if (r < N)
                    *reinterpret_cast<__half2*>(g_cw + (size_t)r * 960 + col) =
                        __floats2half2_rn(acc[i][j][0] + bx, acc[i][j][1] + by);
                if (r + 8 < N)
                    *reinterpret_cast<__half2*>(g_cw + (size_t)(r + 8) * 960 + col) =
                        __floats2half2_rn(acc[i][j][2] + bx, acc[i][j][3] + by);
            }
        }
        __syncthreads();   // before next B overwrite
    }
}

// ================= K5: gather + influence + aggregate (cw smem-cached) ========
__global__ void __launch_bounds__(512) k5_agg(
    const float* __restrict__ q_pts, const float* __restrict__ s_pts,
    const int* __restrict__ neighb_inds,
    const float* __restrict__ kernel_points, float* __restrict__ out, int N)
{
    __shared__ __half cw_s[16 * 960];     // 30720 B
    __shared__ float  kp_s[48];
    __shared__ float  infl_s[512];
    __shared__ int    ind_s[512];
    __shared__ unsigned char nn_s[512];

    const int tid = threadIdx.x;
    const int m0  = blockIdx.x * 16;

    if (tid < 45) kp_s[tid] = kernel_points[tid];

    // stage conv weights for 16 queries: 1920 uint4, coalesced
    {
        const uint4* src = reinterpret_cast<const uint4*>(g_cw + (size_t)m0 * 960);
        uint4* dst = reinterpret_cast<uint4*>(cw_s);
        #pragma unroll
        for (int it = 0; it < 4; it++) {
            int i = it * 512 + tid;
            if (i < 1920 && (m0 + i / 120) < N) dst[i] = src[i];
        }
    }
    __syncthreads();   // kp_s visible to all before metadata (R5 bug fix)

    // metadata: one (m,h) pair per thread
    {
        int m = tid >> 5, h = tid & 31;
        int gm = m0 + m;
        int ind = 0, kb = 0;
        float infl = 0.f;
        if (gm < N) {
            int id = neighb_inds[gm * 32 + h];
            if ((unsigned)id < (unsigned)N) {
                ind = id;
                float qx = q_pts[gm * 3 + 0];
                float qy = q_pts[gm * 3 + 1];
                float qz = q_pts[gm * 3 + 2];
                float nx = s_pts[id * 3 + 0] - qx;
                float ny = s_pts[id * 3 + 1] - qy;
                float nz = s_pts[id * 3 + 2] - qz;
                float best = 1e30f;
                #pragma unroll
                for (int k = 0; k < 15; k++) {
                    float dx = nx - kp_s[k * 3 + 0];
                    float dy = ny - kp_s[k * 3 + 1];
                    float dz = nz - kp_s[k * 3 + 2];
                    float d = fmaf(dx, dx, fmaf(dy, dy, dz * dz));
                    if (d < best) { best = d; kb = k; }
                }
                infl = fmaxf(0.f, 1.f - sqrtf(best) * SIGMA_INV);
            }
        }
        ind_s[tid]  = ind;
        infl_s[tid] = infl;
        nn_s[tid]   = (unsigned char)kb;
    }
    __syncthreads();

    // aggregation: warp owns one query, lane owns channel pair
    {
        const int wid = tid >> 5, lane = tid & 31;
        const int gm = m0 + wid;
        if (gm >= N) return;
        const __half* cw_row = cw_s + wid * 960;
        float ox = 0.f, oy = 0.f;
        const int base = wid * 32;
        #pragma unroll 8
        for (int h = 0; h < 32; h++) {
            float fl = infl_s[base + h];
            int   id = ind_s[base + h];
            int   k  = nn_s[base + h];
            __half2 fh = *reinterpret_cast<const __half2*>(
                g_feats16 + id * 64 + 2 * lane);
            __half2 wh = *reinterpret_cast<const __half2*>(
                cw_row + (k << 6) + 2 * lane);
            float2 f  = __half22float2(fh);
            float2 wf = __half22float2(wh);
            ox = fmaf(f.x, wf.x * fl, ox);
            oy = fmaf(f.y, wf.y * fl, oy);
        }
        *reinterpret_cast<float2*>(out + gm * 64 + 2 * lane) = make_float2(ox, oy);
    }
}

// ================= launch =================
extern "C" void kernel_launch(void* const* d_in, const int* in_sizes, int n_in,
                              void* d_out, int out_size)
{
    const float* q_pts   = (const float*)d_in[0];
    const float* s_pts   = (const float*)d_in[1];
    const float* s_feats = (const float*)d_in[2];
    const int*   neighb  = (const int*)d_in[3];
    const float* kp      = (const float*)d_in[4];
    const float* W1      = (const float*)d_in[5];
    const float* gamma   = (const float*)d_in[6];
    const float* beta    = (const float*)d_in[7];
    const float* W2      = (const float*)d_in[8];
    const float* b2      = (const float*)d_in[9];
    float* out = (float*)d_out;

    const int N   = in_sizes[0] / 3;
    const int nb1 = (N + 127) / 128;

    cudaFuncSetAttribute(k1_feat_mm, cudaFuncAttributeMaxDynamicSharedMemorySize,
                         K1_SMEM_BYTES);
    k1_feat_mm<<<nb1, 256, K1_SMEM_BYTES>>>(s_feats, W1, N);
    k2_bn_tr<<<61, 256>>>(gamma, beta, W2, N, nb1);
    k4_gemm<<<(N + 127) / 128, 256>>>(b2, N);
    k5_agg<<<(N + 15) / 16, 512>>>(q_pts, s_pts, neighb, kp, out, N);
}